// round 2
// baseline (speedup 1.0000x reference)
#include <cuda_runtime.h>
#include <math.h>

// Problem constants (fixed shapes per reference)
#define B_EV   20
#define V_EV   3000
#define KNN_K  40
#define FIN    64
#define PROP   64
#define DIM    4
#define FOUT   128
#define NHITS  (B_EV * V_EV)        // 60000
#define AIN    (2 * PROP + FIN)     // 192

// Scratch (device globals; no allocations allowed)
__device__ float g_feat[NHITS * PROP];       // relu(x@W_prop+b) [N,64]
__device__ float g_coords[NHITS * DIM];      // x@W_sp+b         [N,4]
__device__ int   g_nidx[NHITS * KNN_K];      // global neighbor idx
__device__ float g_dist[NHITS * KNN_K];      // clamped distsq
__device__ float g_a[(size_t)NHITS * AIN];   // GEMM input [N,192]

// ---------------------------------------------------------------------------
// K1: coordinates = x@W_sp + b_sp ; feat = relu(x@W_prop + b_prop)
// 256 threads = 4 hits/block, 64 threads per hit.
// ---------------------------------------------------------------------------
__global__ __launch_bounds__(256)
void k_transform(const float* __restrict__ x,
                 const float* __restrict__ Wp, const float* __restrict__ bp,
                 const float* __restrict__ Ws, const float* __restrict__ bs,
                 float* __restrict__ coords_out)  // may be null
{
    __shared__ float xs[4][FIN];
    int h = threadIdx.x >> 6;
    int j = threadIdx.x & 63;
    int hit = blockIdx.x * 4 + h;
    if (hit < NHITS) xs[h][j] = x[hit * FIN + j];
    __syncthreads();
    if (hit >= NHITS) return;

    // feature transform: thread j computes feat[j]
    float acc = bp[j];
#pragma unroll
    for (int i = 0; i < FIN; i++)
        acc += xs[h][i] * Wp[i * PROP + j];
    g_feat[hit * PROP + j] = fmaxf(acc, 0.0f);

    // spatial transform: threads 0..3 compute coords
    if (j < DIM) {
        float c = bs[j];
#pragma unroll
        for (int i = 0; i < FIN; i++)
            c += xs[h][i] * Ws[i * DIM + j];
        g_coords[hit * DIM + j] = c;
        if (coords_out) coords_out[hit * DIM + j] = c;
    }
}

// ---------------------------------------------------------------------------
// K2: per-event exact KNN (40 nearest excluding self), ordered ascending by
// (dist, index) to match jax.lax.top_k stable tie-break.
// Block = 128 query rows of one event; all 3000 event coords in shared.
// Per-thread max-heap of size 40 in local memory; heapsort at the end.
// ---------------------------------------------------------------------------
__device__ __forceinline__ bool pless(float d1, int i1, float d2, int i2) {
    return (d1 < d2) || (d1 == d2 && i1 < i2);
}

__device__ __forceinline__ void siftdown(float* hd, int* hi, int s, int n) {
    float dv = hd[s];
    int   iv = hi[s];
    while (true) {
        int c = 2 * s + 1;
        if (c >= n) break;
        int c2 = c + 1;
        if (c2 < n && pless(hd[c], hi[c], hd[c2], hi[c2])) c = c2;  // larger child
        if (pless(dv, iv, hd[c], hi[c])) {
            hd[s] = hd[c]; hi[s] = hi[c]; s = c;
        } else break;
    }
    hd[s] = dv;
    hi[s] = iv;
}

__global__ __launch_bounds__(128)
void k_knn(float* __restrict__ nidx_out,   // may be null (float-cast indices)
           float* __restrict__ dist_out)   // may be null
{
    __shared__ float4 cs[V_EV];  // 48000 bytes
    int ev = blockIdx.y;
    int base = ev * V_EV;

    for (int t = threadIdx.x; t < V_EV; t += blockDim.x)
        cs[t] = *(const float4*)&g_coords[(size_t)(base + t) * 4];
    __syncthreads();

    int q = blockIdx.x * blockDim.x + threadIdx.x;
    if (q >= V_EV) return;

    float4 qc = cs[q];
    float qs = ((qc.x * qc.x + qc.y * qc.y) + qc.z * qc.z) + qc.w * qc.w;

    float hd[KNN_K];
    int   hi[KNN_K];
    int cnt = 0;

    for (int w = 0; w < V_EV; w++) {
        float4 c = cs[w];  // broadcast across the warp (uniform w)
        float sqw = ((c.x * c.x + c.y * c.y) + c.z * c.z) + c.w * c.w;
        float dot = ((qc.x * c.x + qc.y * c.y) + qc.z * c.z) + qc.w * c.w;
        float d = (qs + sqw) - 2.0f * dot;
        if (w == q) continue;
        if (cnt < KNN_K) {
            hd[cnt] = d; hi[cnt] = w; cnt++;
            if (cnt == KNN_K) {
                for (int s = KNN_K / 2 - 1; s >= 0; s--)
                    siftdown(hd, hi, s, KNN_K);
            }
        } else if (pless(d, w, hd[0], hi[0])) {
            hd[0] = d; hi[0] = w;
            siftdown(hd, hi, 0, KNN_K);
        }
    }

    // heapsort -> ascending by (d, idx)
    for (int n = KNN_K - 1; n > 0; n--) {
        float td = hd[0]; int ti = hi[0];
        hd[0] = hd[n]; hi[0] = hi[n];
        hd[n] = td;    hi[n] = ti;
        siftdown(hd, hi, 0, n);
    }

    size_t rowoff = (size_t)(base + q) * KNN_K;
    for (int k = 0; k < KNN_K; k++) {
        int gidx = base + hi[k];
        float dd = fmaxf(hd[k], 0.0f);
        g_nidx[rowoff + k] = gidx;
        g_dist[rowoff + k] = dd;
        if (nidx_out) nidx_out[rowoff + k] = (float)gidx;
        if (dist_out) dist_out[rowoff + k] = dd;
    }
}

// ---------------------------------------------------------------------------
// K3: aggregation. a = [mean_k(f_nbr*w)-f, max_k(f_nbr*w)-f, x]  [N,192]
// 256 threads = 4 hits/block, 64 threads (features) per hit.
// ---------------------------------------------------------------------------
__global__ __launch_bounds__(256)
void k_agg(const float* __restrict__ x)
{
    __shared__ float wsh[4][KNN_K];
    __shared__ int   nsh[4][KNN_K];
    int h = threadIdx.x >> 6;
    int p = threadIdx.x & 63;
    int hit = blockIdx.x * 4 + h;

    if (hit < NHITS && p < KNN_K) {
        float dd = g_dist[(size_t)hit * KNN_K + p];
        wsh[h][p] = expf(-10.0f * dd);
        nsh[h][p] = g_nidx[(size_t)hit * KNN_K + p];
    }
    __syncthreads();
    if (hit >= NHITS) return;

    float acc = 0.0f;
    float mx = -INFINITY;
#pragma unroll 8
    for (int k = 0; k < KNN_K; k++) {
        float f = g_feat[(size_t)nsh[h][k] * PROP + p];
        float v = f * wsh[h][k];
        acc += v;
        mx = fmaxf(mx, v);
    }
    float fs = g_feat[(size_t)hit * PROP + p];
    float* arow = &g_a[(size_t)hit * AIN];
    arow[p]        = acc / (float)KNN_K - fs;
    arow[PROP + p] = mx - fs;
    arow[2 * PROP + p] = x[hit * FIN + p];
}

// ---------------------------------------------------------------------------
// K4: out = tanh(a @ W_out + b_out), [60000,192] x [192,128].
// 128x128 tile, BK=16, 256 threads, 8x8 register blocking.
// ---------------------------------------------------------------------------
#define GM 128
#define GK 16

__global__ __launch_bounds__(256)
void k_gemm(const float* __restrict__ W, const float* __restrict__ bias,
            float* __restrict__ out)
{
    __shared__ float As[GK][GM + 4];   // A transposed: As[k][m]
    __shared__ float Bs[GK][FOUT];

    int tid = threadIdx.x;
    int tx = tid & 15;       // output-col group
    int ty = tid >> 4;       // output-row group
    int rowBase = blockIdx.x * GM;

    float acc[8][8];
#pragma unroll
    for (int i = 0; i < 8; i++)
#pragma unroll
        for (int j = 0; j < 8; j++) acc[i][j] = 0.0f;

    for (int kt = 0; kt < AIN; kt += GK) {
        // load A tile: 128 rows x 16 cols = 512 float4, 2 per thread
#pragma unroll
        for (int l = 0; l < 2; l++) {
            int id = tid + l * 256;
            int r = id >> 2;
            int c4 = (id & 3) * 4;
            int grow = rowBase + r;
            float4 v = make_float4(0.f, 0.f, 0.f, 0.f);
            if (grow < NHITS)
                v = *(const float4*)&g_a[(size_t)grow * AIN + kt + c4];
            As[c4 + 0][r] = v.x;
            As[c4 + 1][r] = v.y;
            As[c4 + 2][r] = v.z;
            As[c4 + 3][r] = v.w;
        }
        // load B tile: 16 rows x 128 cols = 512 float4, 2 per thread
#pragma unroll
        for (int l = 0; l < 2; l++) {
            int id = tid + l * 256;
            int r = id >> 5;
            int c = (id & 31) * 4;
            *(float4*)&Bs[r][c] = *(const float4*)&W[(size_t)(kt + r) * FOUT + c];
        }
        __syncthreads();

#pragma unroll
        for (int k = 0; k < GK; k++) {
            float4 a0 = *(const float4*)&As[k][ty * 8];
            float4 a1 = *(const float4*)&As[k][ty * 8 + 4];
            float4 b0 = *(const float4*)&Bs[k][tx * 8];
            float4 b1 = *(const float4*)&Bs[k][tx * 8 + 4];
            float a[8] = {a0.x, a0.y, a0.z, a0.w, a1.x, a1.y, a1.z, a1.w};
            float b[8] = {b0.x, b0.y, b0.z, b0.w, b1.x, b1.y, b1.z, b1.w};
#pragma unroll
            for (int i = 0; i < 8; i++)
#pragma unroll
                for (int j = 0; j < 8; j++)
                    acc[i][j] += a[i] * b[j];
        }
        __syncthreads();
    }

    // epilogue: bias + tanh
    float bv[8];
#pragma unroll
    for (int j = 0; j < 8; j++) bv[j] = bias[tx * 8 + j];

#pragma unroll
    for (int i = 0; i < 8; i++) {
        int grow = rowBase + ty * 8 + i;
        if (grow < NHITS) {
#pragma unroll
            for (int j = 0; j < 8; j++)
                out[(size_t)grow * FOUT + tx * 8 + j] = tanhf(acc[i][j] + bv[j]);
        }
    }
}

// ---------------------------------------------------------------------------
// launch
// ---------------------------------------------------------------------------
extern "C" void kernel_launch(void* const* d_in, const int* in_sizes, int n_in,
                              void* d_out, int out_size)
{
    const float* x  = (const float*)d_in[0];
    // d_in[1] = row_splits (int32) — uniform, derived from constants
    const float* Wp = (const float*)d_in[2];
    const float* bp = (const float*)d_in[3];
    const float* Ws = (const float*)d_in[4];
    const float* bs = (const float*)d_in[5];
    const float* Wo = (const float*)d_in[6];
    const float* bo = (const float*)d_in[7];

    float* out = (float*)d_out;

    // Output layout: assume concat of (out, coordinates, nidx, distsq) flattened
    // in reference-return order, all cast to f32. Fall back to out-only.
    const int full_sz = NHITS * (FOUT + DIM + KNN_K + KNN_K);
    bool full = (out_size == full_sz);
    float* coords_out = full ? out + (size_t)NHITS * FOUT : nullptr;
    float* nidx_out   = full ? coords_out + (size_t)NHITS * DIM : nullptr;
    float* dist_out   = full ? nidx_out + (size_t)NHITS * KNN_K : nullptr;

    k_transform<<<NHITS / 4, 256>>>(x, Wp, bp, Ws, bs, coords_out);
    k_knn<<<dim3((V_EV + 127) / 128, B_EV), 128>>>(nidx_out, dist_out);
    k_agg<<<NHITS / 4, 256>>>(x);
    k_gemm<<<(NHITS + GM - 1) / GM, 256>>>(Wo, bo, out);
}

// round 3
// speedup vs baseline: 5.3303x; 5.3303x over previous
#include <cuda_runtime.h>
#include <math.h>

// Problem constants (fixed shapes per reference)
#define B_EV   20
#define V_EV   3000
#define KNN_K  40
#define FIN    64
#define PROP   64
#define DIM    4
#define FOUT   128
#define NHITS  (B_EV * V_EV)        // 60000
#define AIN    (2 * PROP + FIN)     // 192

typedef unsigned long long ull;

// Scratch (device globals; no allocations allowed)
__device__ float g_feat[NHITS * PROP];       // relu(x@W_prop+b) [N,64]
__device__ float g_coords[NHITS * DIM];      // x@W_sp+b         [N,4]
__device__ float g_cnorm[NHITS];             // |coords|^2
__device__ int   g_nidx[NHITS * KNN_K];      // global neighbor idx
__device__ float g_dist[NHITS * KNN_K];      // clamped distsq
__device__ float g_a[(size_t)NHITS * AIN];   // GEMM input [N,192]

// ---------------------------------------------------------------------------
// K1: coordinates = x@W_sp + b_sp ; feat = relu(x@W_prop + b_prop)
// ---------------------------------------------------------------------------
__global__ __launch_bounds__(256)
void k_transform(const float* __restrict__ x,
                 const float* __restrict__ Wp, const float* __restrict__ bp,
                 const float* __restrict__ Ws, const float* __restrict__ bs,
                 float* __restrict__ coords_out)  // may be null
{
    __shared__ float xs[4][FIN];
    int h = threadIdx.x >> 6;
    int j = threadIdx.x & 63;
    int hit = blockIdx.x * 4 + h;
    if (hit < NHITS) xs[h][j] = x[hit * FIN + j];
    __syncthreads();
    if (hit >= NHITS) return;

    float acc = bp[j];
#pragma unroll
    for (int i = 0; i < FIN; i++)
        acc += xs[h][i] * Wp[i * PROP + j];
    g_feat[hit * PROP + j] = fmaxf(acc, 0.0f);

    if (j < DIM) {
        float c = bs[j];
#pragma unroll
        for (int i = 0; i < FIN; i++)
            c += xs[h][i] * Ws[i * DIM + j];
        g_coords[hit * DIM + j] = c;
        if (coords_out) coords_out[hit * DIM + j] = c;
    }
}

// tiny kernel: per-hit coordinate norm (same FMA grouping as KNN math)
__global__ __launch_bounds__(256)
void k_norm()
{
    int i = blockIdx.x * 256 + threadIdx.x;
    if (i >= NHITS) return;
    float4 c = *(const float4*)&g_coords[(size_t)i * 4];
    g_cnorm[i] = ((c.x * c.x + c.y * c.y) + c.z * c.z) + c.w * c.w;
}

// ---------------------------------------------------------------------------
// K2: per-event exact KNN. One thread per query. Top-40 kept as a 4-ary
// max-heap of packed uint64 keys ((order-flipped dist bits)<<32 | idx) in
// SHARED memory (thread-column layout). Heap root (threshold) cached in a
// register so the hot loop never touches the heap.
// ---------------------------------------------------------------------------
#define KNN_T 128   // threads per block

// replace root with key (key < current root), sift down, return new root value
__device__ __forceinline__ ull heap_replace(ull (*hp)[KNN_T], int tid, ull key)
{
    int s = 0;
    ull rootval = key;
#pragma unroll
    for (int lvl = 0; lvl < 3; lvl++) {
        int c0 = 4 * s + 1;
        if (c0 >= KNN_K) break;
        ull k0 = hp[c0][tid];
        ull k1 = (c0 + 1 < KNN_K) ? hp[c0 + 1][tid] : 0ull;
        ull k2 = (c0 + 2 < KNN_K) ? hp[c0 + 2][tid] : 0ull;
        ull k3 = (c0 + 3 < KNN_K) ? hp[c0 + 3][tid] : 0ull;
        int ci = c0; ull ck = k0;
        if (k1 > ck) { ck = k1; ci = c0 + 1; }
        if (k2 > ck) { ck = k2; ci = c0 + 2; }
        if (k3 > ck) { ck = k3; ci = c0 + 3; }
        if (ck > key) {
            hp[s][tid] = ck;
            if (lvl == 0) rootval = ck;
            s = ci;
        } else break;
    }
    hp[s][tid] = key;
    return rootval;
}

// generic siftdown for heapsort (heap size n)
__device__ __forceinline__ void heap_sift(ull (*hp)[KNN_T], int tid, ull key, int n)
{
    int s = 0;
    while (true) {
        int c0 = 4 * s + 1;
        if (c0 >= n) break;
        ull k0 = hp[c0][tid];
        ull k1 = (c0 + 1 < n) ? hp[c0 + 1][tid] : 0ull;
        ull k2 = (c0 + 2 < n) ? hp[c0 + 2][tid] : 0ull;
        ull k3 = (c0 + 3 < n) ? hp[c0 + 3][tid] : 0ull;
        int ci = c0; ull ck = k0;
        if (k1 > ck) { ck = k1; ci = c0 + 1; }
        if (k2 > ck) { ck = k2; ci = c0 + 2; }
        if (k3 > ck) { ck = k3; ci = c0 + 3; }
        if (ck > key) { hp[s][tid] = ck; s = ci; }
        else break;
    }
    hp[s][tid] = key;
}

__global__ __launch_bounds__(KNN_T)
void k_knn(float* __restrict__ nidx_out,   // may be null (float-cast indices)
           float* __restrict__ dist_out)   // may be null
{
    __shared__ ull hp[KNN_K][KNN_T];   // 40*128*8 = 40960 B

    int ev   = blockIdx.y;
    int base = ev * V_EV;
    int tid  = threadIdx.x;
    int q    = blockIdx.x * KNN_T + tid;
    bool act = (q < V_EV);

#pragma unroll
    for (int k = 0; k < KNN_K; k++) hp[k][tid] = ~0ull;

    const float4* cp = (const float4*)&g_coords[(size_t)base * 4];
    const float*  np = &g_cnorm[base];

    float4 qc = act ? __ldg(cp + q) : make_float4(0.f, 0.f, 0.f, 0.f);
    float  qs = act ? __ldg(np + q) : 0.f;

    ull thr = ~0ull;

    // 3000 = 750 * 4
    for (int w0 = 0; w0 < V_EV; w0 += 4) {
        float4 c0 = __ldg(cp + w0);
        float4 c1 = __ldg(cp + w0 + 1);
        float4 c2 = __ldg(cp + w0 + 2);
        float4 c3 = __ldg(cp + w0 + 3);
        float  n0 = __ldg(np + w0);
        float  n1 = __ldg(np + w0 + 1);
        float  n2 = __ldg(np + w0 + 2);
        float  n3 = __ldg(np + w0 + 3);
        if (!act) continue;

#pragma unroll
        for (int u = 0; u < 4; u++) {
            float4 c = (u == 0) ? c0 : (u == 1) ? c1 : (u == 2) ? c2 : c3;
            float  n = (u == 0) ? n0 : (u == 1) ? n1 : (u == 2) ? n2 : n3;
            int    w = w0 + u;
            float dot = ((qc.x * c.x + qc.y * c.y) + qc.z * c.z) + qc.w * c.w;
            float d   = (qs + n) - 2.0f * dot;
            unsigned int b = __float_as_uint(d);
            b ^= (unsigned int)(((int)b >> 31) | 0x80000000);
            ull key = ((ull)b << 32) | (unsigned int)w;
            if (w == q) key = ~0ull;
            if (key < thr)
                thr = heap_replace(hp, tid, key);
        }
    }

    if (!act) return;

    // heapsort -> hp[0..39] ascending by (dist, idx)
    for (int n = KNN_K - 1; n > 0; n--) {
        ull top  = hp[0][tid];
        ull last = hp[n][tid];
        hp[n][tid] = top;
        heap_sift(hp, tid, last, n);
    }

    size_t rowoff = (size_t)(base + q) * KNN_K;
#pragma unroll 8
    for (int k = 0; k < KNN_K; k++) {
        ull key = hp[k][tid];
        unsigned int widx = (unsigned int)key;
        unsigned int b    = (unsigned int)(key >> 32);
        unsigned int m    = (unsigned int)((int)b >> 31);  // all-ones if d was >= 0
        b ^= (m & 0x80000000u) | (~m);
        float dd = fmaxf(__uint_as_float(b), 0.0f);
        int gidx = base + (int)widx;
        g_nidx[rowoff + k] = gidx;
        g_dist[rowoff + k] = dd;
        if (nidx_out) nidx_out[rowoff + k] = (float)gidx;
        if (dist_out) dist_out[rowoff + k] = dd;
    }
}

// ---------------------------------------------------------------------------
// K3: aggregation. a = [mean_k(f_nbr*w)-f, max_k(f_nbr*w)-f, x]  [N,192]
// ---------------------------------------------------------------------------
__global__ __launch_bounds__(256)
void k_agg(const float* __restrict__ x)
{
    __shared__ float wsh[4][KNN_K];
    __shared__ int   nsh[4][KNN_K];
    int h = threadIdx.x >> 6;
    int p = threadIdx.x & 63;
    int hit = blockIdx.x * 4 + h;

    if (hit < NHITS && p < KNN_K) {
        float dd = g_dist[(size_t)hit * KNN_K + p];
        wsh[h][p] = expf(-10.0f * dd);
        nsh[h][p] = g_nidx[(size_t)hit * KNN_K + p];
    }
    __syncthreads();
    if (hit >= NHITS) return;

    float acc = 0.0f;
    float mx = -INFINITY;
#pragma unroll 8
    for (int k = 0; k < KNN_K; k++) {
        float f = g_feat[(size_t)nsh[h][k] * PROP + p];
        float v = f * wsh[h][k];
        acc += v;
        mx = fmaxf(mx, v);
    }
    float fs = g_feat[(size_t)hit * PROP + p];
    float* arow = &g_a[(size_t)hit * AIN];
    arow[p]        = acc / (float)KNN_K - fs;
    arow[PROP + p] = mx - fs;
    arow[2 * PROP + p] = x[hit * FIN + p];
}

// ---------------------------------------------------------------------------
// K4: out = tanh(a @ W_out + b_out), [60000,192] x [192,128].
// ---------------------------------------------------------------------------
#define GM 128
#define GK 16

__global__ __launch_bounds__(256)
void k_gemm(const float* __restrict__ W, const float* __restrict__ bias,
            float* __restrict__ out)
{
    __shared__ float As[GK][GM + 4];
    __shared__ float Bs[GK][FOUT];

    int tid = threadIdx.x;
    int tx = tid & 15;
    int ty = tid >> 4;
    int rowBase = blockIdx.x * GM;

    float acc[8][8];
#pragma unroll
    for (int i = 0; i < 8; i++)
#pragma unroll
        for (int j = 0; j < 8; j++) acc[i][j] = 0.0f;

    for (int kt = 0; kt < AIN; kt += GK) {
#pragma unroll
        for (int l = 0; l < 2; l++) {
            int id = tid + l * 256;
            int r = id >> 2;
            int c4 = (id & 3) * 4;
            int grow = rowBase + r;
            float4 v = make_float4(0.f, 0.f, 0.f, 0.f);
            if (grow < NHITS)
                v = *(const float4*)&g_a[(size_t)grow * AIN + kt + c4];
            As[c4 + 0][r] = v.x;
            As[c4 + 1][r] = v.y;
            As[c4 + 2][r] = v.z;
            As[c4 + 3][r] = v.w;
        }
#pragma unroll
        for (int l = 0; l < 2; l++) {
            int id = tid + l * 256;
            int r = id >> 5;
            int c = (id & 31) * 4;
            *(float4*)&Bs[r][c] = *(const float4*)&W[(size_t)(kt + r) * FOUT + c];
        }
        __syncthreads();

#pragma unroll
        for (int k = 0; k < GK; k++) {
            float4 a0 = *(const float4*)&As[k][ty * 8];
            float4 a1 = *(const float4*)&As[k][ty * 8 + 4];
            float4 b0 = *(const float4*)&Bs[k][tx * 8];
            float4 b1 = *(const float4*)&Bs[k][tx * 8 + 4];
            float a[8] = {a0.x, a0.y, a0.z, a0.w, a1.x, a1.y, a1.z, a1.w};
            float b[8] = {b0.x, b0.y, b0.z, b0.w, b1.x, b1.y, b1.z, b1.w};
#pragma unroll
            for (int i = 0; i < 8; i++)
#pragma unroll
                for (int j = 0; j < 8; j++)
                    acc[i][j] += a[i] * b[j];
        }
        __syncthreads();
    }

    float bv[8];
#pragma unroll
    for (int j = 0; j < 8; j++) bv[j] = bias[tx * 8 + j];

#pragma unroll
    for (int i = 0; i < 8; i++) {
        int grow = rowBase + ty * 8 + i;
        if (grow < NHITS) {
#pragma unroll
            for (int j = 0; j < 8; j++)
                out[(size_t)grow * FOUT + tx * 8 + j] = tanhf(acc[i][j] + bv[j]);
        }
    }
}

// ---------------------------------------------------------------------------
// launch
// ---------------------------------------------------------------------------
extern "C" void kernel_launch(void* const* d_in, const int* in_sizes, int n_in,
                              void* d_out, int out_size)
{
    const float* x  = (const float*)d_in[0];
    const float* Wp = (const float*)d_in[2];
    const float* bp = (const float*)d_in[3];
    const float* Ws = (const float*)d_in[4];
    const float* bs = (const float*)d_in[5];
    const float* Wo = (const float*)d_in[6];
    const float* bo = (const float*)d_in[7];

    float* out = (float*)d_out;

    const int full_sz = NHITS * (FOUT + DIM + KNN_K + KNN_K);
    bool full = (out_size == full_sz);
    float* coords_out = full ? out + (size_t)NHITS * FOUT : nullptr;
    float* nidx_out   = full ? coords_out + (size_t)NHITS * DIM : nullptr;
    float* dist_out   = full ? nidx_out + (size_t)NHITS * KNN_K : nullptr;

    k_transform<<<NHITS / 4, 256>>>(x, Wp, bp, Ws, bs, coords_out);
    k_norm<<<(NHITS + 255) / 256, 256>>>();
    k_knn<<<dim3((V_EV + KNN_T - 1) / KNN_T, B_EV), KNN_T>>>(nidx_out, dist_out);
    k_agg<<<NHITS / 4, 256>>>(x);
    k_gemm<<<(NHITS + GM - 1) / GM, 256>>>(Wo, bo, out);
}

// round 5
// speedup vs baseline: 8.5764x; 1.6090x over previous
#include <cuda_runtime.h>
#include <math.h>

// Problem constants (fixed shapes per reference)
#define B_EV   20
#define V_EV   3000
#define KNN_K  40
#define FIN    64
#define PROP   64
#define DIM    4
#define FOUT   128
#define NHITS  (B_EV * V_EV)        // 60000
#define AIN    (2 * PROP + FIN)     // 192

typedef unsigned long long ull;

// Scratch (device globals; no allocations allowed)
__device__ float g_feat[NHITS * PROP];       // relu(x@W_prop+b) [N,64]
__device__ float g_coords[NHITS * DIM];      // x@W_sp+b         [N,4]
__device__ float g_cnorm[NHITS];             // |coords|^2
__device__ int   g_nidx[NHITS * KNN_K];      // global neighbor idx
__device__ float g_dist[NHITS * KNN_K];      // clamped distsq
__device__ float g_a[(size_t)NHITS * AIN];   // GEMM input [N,192]

// ---------------------------------------------------------------------------
// K1: coordinates = x@W_sp + b_sp ; feat = relu(x@W_prop + b_prop)
// ---------------------------------------------------------------------------
__global__ __launch_bounds__(256)
void k_transform(const float* __restrict__ x,
                 const float* __restrict__ Wp, const float* __restrict__ bp,
                 const float* __restrict__ Ws, const float* __restrict__ bs,
                 float* __restrict__ coords_out)  // may be null
{
    __shared__ float xs[4][FIN];
    int h = threadIdx.x >> 6;
    int j = threadIdx.x & 63;
    int hit = blockIdx.x * 4 + h;
    if (hit < NHITS) xs[h][j] = x[hit * FIN + j];
    __syncthreads();
    if (hit >= NHITS) return;

    float acc = bp[j];
#pragma unroll
    for (int i = 0; i < FIN; i++)
        acc += xs[h][i] * Wp[i * PROP + j];
    g_feat[hit * PROP + j] = fmaxf(acc, 0.0f);

    if (j < DIM) {
        float c = bs[j];
#pragma unroll
        for (int i = 0; i < FIN; i++)
            c += xs[h][i] * Ws[i * DIM + j];
        g_coords[hit * DIM + j] = c;
        if (coords_out) coords_out[hit * DIM + j] = c;
    }
}

// per-hit coordinate norm (same FMA grouping as KNN math)
__global__ __launch_bounds__(256)
void k_norm()
{
    int i = blockIdx.x * 256 + threadIdx.x;
    if (i >= NHITS) return;
    float4 c = *(const float4*)&g_coords[(size_t)i * 4];
    g_cnorm[i] = ((c.x * c.x + c.y * c.y) + c.z * c.z) + c.w * c.w;
}

// ---------------------------------------------------------------------------
// K2: per-event exact KNN. One thread per query. Hot loop only FILTERS
// (key < thr, thr possibly stale) and appends passing keys to a per-lane
// shared ring. Ring is flushed into the per-thread 4-ary shared max-heap
// only when a ballot says some lane's ring is near capacity. Staleness of
// thr only admits extra candidates; flush re-checks against the live root,
// so the final heap content is exact.
// ---------------------------------------------------------------------------
#define KNN_T    128   // threads per block
#define RING_CAP 8

// replace root with key (key < current root), sift down, return new root value
__device__ __forceinline__ ull heap_replace(ull (*hp)[KNN_T], int tid, ull key)
{
    int s = 0;
    ull rootval = key;
#pragma unroll
    for (int lvl = 0; lvl < 3; lvl++) {
        int c0 = 4 * s + 1;
        if (c0 >= KNN_K) break;
        ull k0 = hp[c0][tid];
        ull k1 = (c0 + 1 < KNN_K) ? hp[c0 + 1][tid] : 0ull;
        ull k2 = (c0 + 2 < KNN_K) ? hp[c0 + 2][tid] : 0ull;
        ull k3 = (c0 + 3 < KNN_K) ? hp[c0 + 3][tid] : 0ull;
        int ci = c0; ull ck = k0;
        if (k1 > ck) { ck = k1; ci = c0 + 1; }
        if (k2 > ck) { ck = k2; ci = c0 + 2; }
        if (k3 > ck) { ck = k3; ci = c0 + 3; }
        if (ck > key) {
            hp[s][tid] = ck;
            if (lvl == 0) rootval = ck;
            s = ci;
        } else break;
    }
    hp[s][tid] = key;
    return rootval;
}

// generic siftdown for heapsort (heap size n)
__device__ __forceinline__ void heap_sift(ull (*hp)[KNN_T], int tid, ull key, int n)
{
    int s = 0;
    while (true) {
        int c0 = 4 * s + 1;
        if (c0 >= n) break;
        ull k0 = hp[c0][tid];
        ull k1 = (c0 + 1 < n) ? hp[c0 + 1][tid] : 0ull;
        ull k2 = (c0 + 2 < n) ? hp[c0 + 2][tid] : 0ull;
        ull k3 = (c0 + 3 < n) ? hp[c0 + 3][tid] : 0ull;
        int ci = c0; ull ck = k0;
        if (k1 > ck) { ck = k1; ci = c0 + 1; }
        if (k2 > ck) { ck = k2; ci = c0 + 2; }
        if (k3 > ck) { ck = k3; ci = c0 + 3; }
        if (ck > key) { hp[s][tid] = ck; s = ci; }
        else break;
    }
    hp[s][tid] = key;
}

__global__ __launch_bounds__(KNN_T)
void k_knn(float* __restrict__ nidx_out,   // may be null (float-cast indices)
           float* __restrict__ dist_out)   // may be null
{
    __shared__ ull hp[KNN_K][KNN_T];       // 40*128*8 = 40960 B
    __shared__ ull ring[RING_CAP][KNN_T];  //  8*128*8 =  8192 B  (total 49152 = max)

    int ev   = blockIdx.y;
    int base = ev * V_EV;
    int tid  = threadIdx.x;
    int q    = blockIdx.x * KNN_T + tid;
    bool act = (q < V_EV);

#pragma unroll
    for (int k = 0; k < KNN_K; k++) hp[k][tid] = ~0ull;

    const float4* cp = (const float4*)&g_coords[(size_t)base * 4];
    const float*  np = &g_cnorm[base];

    float4 qc = act ? __ldg(cp + q) : make_float4(0.f, 0.f, 0.f, 0.f);
    float  qs = act ? __ldg(np + q) : 0.f;

    ull thr = ~0ull;   // filter threshold (may be stale vs heap root)
    int pend = 0;      // entries pending in this lane's ring

    for (int w0 = 0; w0 < V_EV; w0 += 4) {
        float4 c0 = __ldg(cp + w0);
        float4 c1 = __ldg(cp + w0 + 1);
        float4 c2 = __ldg(cp + w0 + 2);
        float4 c3 = __ldg(cp + w0 + 3);
        float  n0 = __ldg(np + w0);
        float  n1 = __ldg(np + w0 + 1);
        float  n2 = __ldg(np + w0 + 2);
        float  n3 = __ldg(np + w0 + 3);

        if (act) {
#pragma unroll
            for (int u = 0; u < 4; u++) {
                float4 c = (u == 0) ? c0 : (u == 1) ? c1 : (u == 2) ? c2 : c3;
                float  n = (u == 0) ? n0 : (u == 1) ? n1 : (u == 2) ? n2 : n3;
                int    w = w0 + u;
                float dot = ((qc.x * c.x + qc.y * c.y) + qc.z * c.z) + qc.w * c.w;
                float d   = (qs + n) - 2.0f * dot;
                unsigned int b = __float_as_uint(d);
                b ^= (unsigned int)(((int)b >> 31) | 0x80000000);
                ull key = ((ull)b << 32) | (unsigned int)w;
                if (w == q) key = ~0ull;
                if (key < thr) {          // predicated append, no heap touch
                    ring[pend][tid] = key;
                    pend++;
                }
            }
        }

        // flush when any lane's ring is near capacity (can gain 4/group)
        if (__any_sync(0xffffffffu, pend > RING_CAP - 4)) {
#pragma unroll 1
            for (int j = 0; j < pend; j++) {
                ull key = ring[j][tid];
                if (key < thr) thr = heap_replace(hp, tid, key);
            }
            pend = 0;
        }
    }

    // final flush
#pragma unroll 1
    for (int j = 0; j < pend; j++) {
        ull key = ring[j][tid];
        if (key < thr) thr = heap_replace(hp, tid, key);
    }

    if (!act) return;

    // heapsort -> hp[0..39] ascending by (dist, idx)
    for (int n = KNN_K - 1; n > 0; n--) {
        ull top  = hp[0][tid];
        ull last = hp[n][tid];
        hp[n][tid] = top;
        heap_sift(hp, tid, last, n);
    }

    size_t rowoff = (size_t)(base + q) * KNN_K;
#pragma unroll 8
    for (int k = 0; k < KNN_K; k++) {
        ull key = hp[k][tid];
        unsigned int widx = (unsigned int)key;
        unsigned int b    = (unsigned int)(key >> 32);
        unsigned int m    = (unsigned int)((int)b >> 31);  // all-ones if d was >= 0
        b ^= (m & 0x80000000u) | (~m);
        float dd = fmaxf(__uint_as_float(b), 0.0f);
        int gidx = base + (int)widx;
        g_nidx[rowoff + k] = gidx;
        g_dist[rowoff + k] = dd;
        if (nidx_out) nidx_out[rowoff + k] = (float)gidx;
        if (dist_out) dist_out[rowoff + k] = dd;
    }
}

// ---------------------------------------------------------------------------
// K3: aggregation. a = [mean_k(f_nbr*w)-f, max_k(f_nbr*w)-f, x]  [N,192]
// ---------------------------------------------------------------------------
__global__ __launch_bounds__(256)
void k_agg(const float* __restrict__ x)
{
    __shared__ float wsh[4][KNN_K];
    __shared__ int   nsh[4][KNN_K];
    int h = threadIdx.x >> 6;
    int p = threadIdx.x & 63;
    int hit = blockIdx.x * 4 + h;

    if (hit < NHITS && p < KNN_K) {
        float dd = g_dist[(size_t)hit * KNN_K + p];
        wsh[h][p] = expf(-10.0f * dd);
        nsh[h][p] = g_nidx[(size_t)hit * KNN_K + p];
    }
    __syncthreads();
    if (hit >= NHITS) return;

    float acc = 0.0f;
    float mx = -INFINITY;
#pragma unroll 8
    for (int k = 0; k < KNN_K; k++) {
        float f = g_feat[(size_t)nsh[h][k] * PROP + p];
        float v = f * wsh[h][k];
        acc += v;
        mx = fmaxf(mx, v);
    }
    float fs = g_feat[(size_t)hit * PROP + p];
    float* arow = &g_a[(size_t)hit * AIN];
    arow[p]        = acc / (float)KNN_K - fs;
    arow[PROP + p] = mx - fs;
    arow[2 * PROP + p] = x[hit * FIN + p];
}

// ---------------------------------------------------------------------------
// K4: out = tanh(a @ W_out + b_out), [60000,192] x [192,128].
// ---------------------------------------------------------------------------
#define GM 128
#define GK 16

__global__ __launch_bounds__(256)
void k_gemm(const float* __restrict__ W, const float* __restrict__ bias,
            float* __restrict__ out)
{
    __shared__ float As[GK][GM + 4];
    __shared__ float Bs[GK][FOUT];

    int tid = threadIdx.x;
    int tx = tid & 15;
    int ty = tid >> 4;
    int rowBase = blockIdx.x * GM;

    float acc[8][8];
#pragma unroll
    for (int i = 0; i < 8; i++)
#pragma unroll
        for (int j = 0; j < 8; j++) acc[i][j] = 0.0f;

    for (int kt = 0; kt < AIN; kt += GK) {
#pragma unroll
        for (int l = 0; l < 2; l++) {
            int id = tid + l * 256;
            int r = id >> 2;
            int c4 = (id & 3) * 4;
            int grow = rowBase + r;
            float4 v = make_float4(0.f, 0.f, 0.f, 0.f);
            if (grow < NHITS)
                v = *(const float4*)&g_a[(size_t)grow * AIN + kt + c4];
            As[c4 + 0][r] = v.x;
            As[c4 + 1][r] = v.y;
            As[c4 + 2][r] = v.z;
            As[c4 + 3][r] = v.w;
        }
#pragma unroll
        for (int l = 0; l < 2; l++) {
            int id = tid + l * 256;
            int r = id >> 5;
            int c = (id & 31) * 4;
            *(float4*)&Bs[r][c] = *(const float4*)&W[(size_t)(kt + r) * FOUT + c];
        }
        __syncthreads();

#pragma unroll
        for (int k = 0; k < GK; k++) {
            float4 a0 = *(const float4*)&As[k][ty * 8];
            float4 a1 = *(const float4*)&As[k][ty * 8 + 4];
            float4 b0 = *(const float4*)&Bs[k][tx * 8];
            float4 b1 = *(const float4*)&Bs[k][tx * 8 + 4];
            float a[8] = {a0.x, a0.y, a0.z, a0.w, a1.x, a1.y, a1.z, a1.w};
            float b[8] = {b0.x, b0.y, b0.z, b0.w, b1.x, b1.y, b1.z, b1.w};
#pragma unroll
            for (int i = 0; i < 8; i++)
#pragma unroll
                for (int j = 0; j < 8; j++)
                    acc[i][j] += a[i] * b[j];
        }
        __syncthreads();
    }

    float bv[8];
#pragma unroll
    for (int j = 0; j < 8; j++) bv[j] = bias[tx * 8 + j];

#pragma unroll
    for (int i = 0; i < 8; i++) {
        int grow = rowBase + ty * 8 + i;
        if (grow < NHITS) {
#pragma unroll
            for (int j = 0; j < 8; j++)
                out[(size_t)grow * FOUT + tx * 8 + j] = tanhf(acc[i][j] + bv[j]);
        }
    }
}

// ---------------------------------------------------------------------------
// launch
// ---------------------------------------------------------------------------
extern "C" void kernel_launch(void* const* d_in, const int* in_sizes, int n_in,
                              void* d_out, int out_size)
{
    const float* x  = (const float*)d_in[0];
    const float* Wp = (const float*)d_in[2];
    const float* bp = (const float*)d_in[3];
    const float* Ws = (const float*)d_in[4];
    const float* bs = (const float*)d_in[5];
    const float* Wo = (const float*)d_in[6];
    const float* bo = (const float*)d_in[7];

    float* out = (float*)d_out;

    const int full_sz = NHITS * (FOUT + DIM + KNN_K + KNN_K);
    bool full = (out_size == full_sz);
    float* coords_out = full ? out + (size_t)NHITS * FOUT : nullptr;
    float* nidx_out   = full ? coords_out + (size_t)NHITS * DIM : nullptr;
    float* dist_out   = full ? nidx_out + (size_t)NHITS * KNN_K : nullptr;

    k_transform<<<NHITS / 4, 256>>>(x, Wp, bp, Ws, bs, coords_out);
    k_norm<<<(NHITS + 255) / 256, 256>>>();
    k_knn<<<dim3((V_EV + KNN_T - 1) / KNN_T, B_EV), KNN_T>>>(nidx_out, dist_out);
    k_agg<<<NHITS / 4, 256>>>(x);
    k_gemm<<<(NHITS + GM - 1) / GM, 256>>>(Wo, bo, out);
}

// round 7
// speedup vs baseline: 9.6952x; 1.1305x over previous
#include <cuda_runtime.h>
#include <math.h>

// Problem constants (fixed shapes per reference)
#define B_EV   20
#define V_EV   3000
#define KNN_K  40
#define FIN    64
#define PROP   64
#define DIM    4
#define FOUT   128
#define NHITS  (B_EV * V_EV)        // 60000
#define AIN    (2 * PROP + FIN)     // 192

typedef unsigned long long ull;

// Scratch (device globals; no allocations allowed)
__device__ float g_feat[NHITS * PROP];       // relu(x@W_prop+b) [N,64]
__device__ float g_coords[NHITS * DIM];      // x@W_sp+b         [N,4] (AoS)
__device__ __align__(16) float g_cx[NHITS];  // SoA coords + norm (16B-aligned
__device__ __align__(16) float g_cy[NHITS];  //  for LDG.128 in the KNN loop)
__device__ __align__(16) float g_cz[NHITS];
__device__ __align__(16) float g_cw[NHITS];
__device__ __align__(16) float g_cn[NHITS];
__device__ int   g_nidx[NHITS * KNN_K];      // global neighbor idx
__device__ float g_dist[NHITS * KNN_K];      // clamped distsq
__device__ float g_a[(size_t)NHITS * AIN];   // GEMM input [N,192]

// ---- packed f32x2 helpers (ptxas emits FFMA2/FADD2 only via explicit PTX) ----
__device__ __forceinline__ ull f2_mul(ull a, ull b) {
    ull r; asm("mul.rn.f32x2 %0, %1, %2;" : "=l"(r) : "l"(a), "l"(b)); return r;
}
__device__ __forceinline__ ull f2_add(ull a, ull b) {
    ull r; asm("add.rn.f32x2 %0, %1, %2;" : "=l"(r) : "l"(a), "l"(b)); return r;
}
__device__ __forceinline__ ull f2_fma(ull a, ull b, ull c) {
    ull r; asm("fma.rn.f32x2 %0, %1, %2, %3;" : "=l"(r) : "l"(a), "l"(b), "l"(c)); return r;
}
__device__ __forceinline__ ull f2_bcast(float a) {
    ull r; asm("mov.b64 %0, {%1, %1};" : "=l"(r) : "f"(a)); return r;
}
__device__ __forceinline__ void f2_unpack(ull v, float& a, float& b) {
    asm("mov.b64 {%0, %1}, %2;" : "=f"(a), "=f"(b) : "l"(v));
}

// ---------------------------------------------------------------------------
// K1: coordinates = x@W_sp + b_sp ; feat = relu(x@W_prop + b_prop)
// ---------------------------------------------------------------------------
__global__ __launch_bounds__(256)
void k_transform(const float* __restrict__ x,
                 const float* __restrict__ Wp, const float* __restrict__ bp,
                 const float* __restrict__ Ws, const float* __restrict__ bs,
                 float* __restrict__ coords_out)  // may be null
{
    __shared__ float xs[4][FIN];
    int h = threadIdx.x >> 6;
    int j = threadIdx.x & 63;
    int hit = blockIdx.x * 4 + h;
    if (hit < NHITS) xs[h][j] = x[hit * FIN + j];
    __syncthreads();
    if (hit >= NHITS) return;

    float acc = bp[j];
#pragma unroll
    for (int i = 0; i < FIN; i++)
        acc += xs[h][i] * Wp[i * PROP + j];
    g_feat[hit * PROP + j] = fmaxf(acc, 0.0f);

    if (j < DIM) {
        float c = bs[j];
#pragma unroll
        for (int i = 0; i < FIN; i++)
            c += xs[h][i] * Ws[i * DIM + j];
        g_coords[hit * DIM + j] = c;
        if (coords_out) coords_out[hit * DIM + j] = c;
    }
}

// AoS -> SoA + per-hit norm (same FMA grouping as KNN math)
__global__ __launch_bounds__(256)
void k_soa()
{
    int i = blockIdx.x * 256 + threadIdx.x;
    if (i >= NHITS) return;
    float4 c = *(const float4*)&g_coords[(size_t)i * 4];
    g_cx[i] = c.x; g_cy[i] = c.y; g_cz[i] = c.z; g_cw[i] = c.w;
    g_cn[i] = ((c.x * c.x + c.y * c.y) + c.z * c.z) + c.w * c.w;
}

// ---------------------------------------------------------------------------
// K2: per-event exact KNN. One thread per query. Hot loop: packed f32x2
// distance math over SoA coords, float-domain threshold filter, passing
// candidates appended to a per-lane shared ring. Ring flushed into the
// per-thread 4-ary shared max-heap when a ballot says a lane's ring is near
// capacity; flush re-checks the exact 64-bit key vs the live root and skips
// the self index, so the final heap is exact.
// ---------------------------------------------------------------------------
#define KNN_T    128   // threads per block
#define RING_CAP 8

__device__ __forceinline__ ull heap_replace(ull (*hp)[KNN_T], int tid, ull key)
{
    int s = 0;
    ull rootval = key;
#pragma unroll
    for (int lvl = 0; lvl < 3; lvl++) {
        int c0 = 4 * s + 1;
        if (c0 >= KNN_K) break;
        ull k0 = hp[c0][tid];
        ull k1 = (c0 + 1 < KNN_K) ? hp[c0 + 1][tid] : 0ull;
        ull k2 = (c0 + 2 < KNN_K) ? hp[c0 + 2][tid] : 0ull;
        ull k3 = (c0 + 3 < KNN_K) ? hp[c0 + 3][tid] : 0ull;
        int ci = c0; ull ck = k0;
        if (k1 > ck) { ck = k1; ci = c0 + 1; }
        if (k2 > ck) { ck = k2; ci = c0 + 2; }
        if (k3 > ck) { ck = k3; ci = c0 + 3; }
        if (ck > key) {
            hp[s][tid] = ck;
            if (lvl == 0) rootval = ck;
            s = ci;
        } else break;
    }
    hp[s][tid] = key;
    return rootval;
}

__device__ __forceinline__ void heap_sift(ull (*hp)[KNN_T], int tid, ull key, int n)
{
    int s = 0;
    while (true) {
        int c0 = 4 * s + 1;
        if (c0 >= n) break;
        ull k0 = hp[c0][tid];
        ull k1 = (c0 + 1 < n) ? hp[c0 + 1][tid] : 0ull;
        ull k2 = (c0 + 2 < n) ? hp[c0 + 2][tid] : 0ull;
        ull k3 = (c0 + 3 < n) ? hp[c0 + 3][tid] : 0ull;
        int ci = c0; ull ck = k0;
        if (k1 > ck) { ck = k1; ci = c0 + 1; }
        if (k2 > ck) { ck = k2; ci = c0 + 2; }
        if (k3 > ck) { ck = k3; ci = c0 + 3; }
        if (ck > key) { hp[s][tid] = ck; s = ci; }
        else break;
    }
    hp[s][tid] = key;
}

// unflip: recover float bits from order-flipped encoding
__device__ __forceinline__ float key_to_dist(unsigned int b)
{
    unsigned int m = (unsigned int)((int)b >> 31);
    b ^= (m & 0x80000000u) | (~m);
    return __uint_as_float(b);
}

__global__ __launch_bounds__(KNN_T)
void k_knn(float* __restrict__ nidx_out,   // may be null (float-cast indices)
           float* __restrict__ dist_out)   // may be null
{
    __shared__ ull hp[KNN_K][KNN_T];       // 40*128*8 = 40960 B
    __shared__ ull ring[RING_CAP][KNN_T];  //  8*128*8 =  8192 B  (total 49152 = max)

    int ev   = blockIdx.y;
    int base = ev * V_EV;
    int tid  = threadIdx.x;
    int q    = blockIdx.x * KNN_T + tid;
    bool act = (q < V_EV);

#pragma unroll
    for (int k = 0; k < KNN_K; k++) hp[k][tid] = ~0ull;

    const float* px = &g_cx[base];
    const float* py = &g_cy[base];
    const float* pz = &g_cz[base];
    const float* pw = &g_cw[base];
    const float* pn = &g_cn[base];

    float qx = act ? __ldg(px + q) : 0.f;
    float qy = act ? __ldg(py + q) : 0.f;
    float qz = act ? __ldg(pz + q) : 0.f;
    float qw = act ? __ldg(pw + q) : 0.f;
    float qs = act ? __ldg(pn + q) : 0.f;

    ull qx2 = f2_bcast(qx), qy2 = f2_bcast(qy);
    ull qz2 = f2_bcast(qz), qw2 = f2_bcast(qw);
    ull qs2 = f2_bcast(qs);
    ull m2  = f2_bcast(-2.0f);

    ull   thr   = ~0ull;                      // exact 64-bit threshold (heap root)
    float thr_f = act ? INFINITY : -INFINITY; // float-domain filter threshold
    int   pend  = 0;

    for (int w0 = 0; w0 < V_EV; w0 += 4) {
        ulonglong2 X = *(const ulonglong2*)(px + w0);  // (x0,x1),(x2,x3)
        ulonglong2 Y = *(const ulonglong2*)(py + w0);
        ulonglong2 Z = *(const ulonglong2*)(pz + w0);
        ulonglong2 W = *(const ulonglong2*)(pw + w0);
        ulonglong2 N = *(const ulonglong2*)(pn + w0);

        // pair 0-1
        ull dot01 = f2_mul(qx2, X.x);
        dot01 = f2_fma(qy2, Y.x, dot01);
        dot01 = f2_fma(qz2, Z.x, dot01);
        dot01 = f2_fma(qw2, W.x, dot01);
        ull d01 = f2_fma(m2, dot01, f2_add(qs2, N.x));
        // pair 2-3
        ull dot23 = f2_mul(qx2, X.y);
        dot23 = f2_fma(qy2, Y.y, dot23);
        dot23 = f2_fma(qz2, Z.y, dot23);
        dot23 = f2_fma(qw2, W.y, dot23);
        ull d23 = f2_fma(m2, dot23, f2_add(qs2, N.y));

        float d0, d1, d2, d3;
        f2_unpack(d01, d0, d1);
        f2_unpack(d23, d2, d3);

#pragma unroll
        for (int u = 0; u < 4; u++) {
            float d = (u == 0) ? d0 : (u == 1) ? d1 : (u == 2) ? d2 : d3;
            if (d <= thr_f) {                 // rare path: pack + append
                unsigned int b = __float_as_uint(d);
                b ^= (unsigned int)(((int)b >> 31) | 0x80000000);
                ring[pend][tid] = ((ull)b << 32) | (unsigned int)(w0 + u);
                pend++;
            }
        }

        // flush when any lane's ring is near capacity (can gain 4/group)
        if (__any_sync(0xffffffffu, pend > RING_CAP - 4)) {
#pragma unroll 1
            for (int j = 0; j < pend; j++) {
                ull key = ring[j][tid];
                if ((unsigned int)key == (unsigned int)q) continue;  // self
                if (key < thr) thr = heap_replace(hp, tid, key);
            }
            pend = 0;
            // sentinel root (heap not yet full) must keep the filter open
            thr_f = (!act) ? -INFINITY
                  : (thr == ~0ull) ? INFINITY
                  : key_to_dist((unsigned int)(thr >> 32));
        }
    }

    // final flush
#pragma unroll 1
    for (int j = 0; j < pend; j++) {
        ull key = ring[j][tid];
        if ((unsigned int)key == (unsigned int)q) continue;
        if (key < thr) thr = heap_replace(hp, tid, key);
    }

    if (!act) return;

    // heapsort -> hp[0..39] ascending by (dist, idx)
    for (int n = KNN_K - 1; n > 0; n--) {
        ull top  = hp[0][tid];
        ull last = hp[n][tid];
        hp[n][tid] = top;
        heap_sift(hp, tid, last, n);
    }

    size_t rowoff = (size_t)(base + q) * KNN_K;
#pragma unroll 8
    for (int k = 0; k < KNN_K; k++) {
        ull key = hp[k][tid];
        unsigned int widx = (unsigned int)key;
        float dd = fmaxf(key_to_dist((unsigned int)(key >> 32)), 0.0f);
        int gidx = base + (int)widx;
        g_nidx[rowoff + k] = gidx;
        g_dist[rowoff + k] = dd;
        if (nidx_out) nidx_out[rowoff + k] = (float)gidx;
        if (dist_out) dist_out[rowoff + k] = dd;
    }
}

// ---------------------------------------------------------------------------
// K3: aggregation. a = [mean_k(f_nbr*w)-f, max_k(f_nbr*w)-f, x]  [N,192]
// ---------------------------------------------------------------------------
__global__ __launch_bounds__(256)
void k_agg(const float* __restrict__ x)
{
    __shared__ float wsh[4][KNN_K];
    __shared__ int   nsh[4][KNN_K];
    int h = threadIdx.x >> 6;
    int p = threadIdx.x & 63;
    int hit = blockIdx.x * 4 + h;

    if (hit < NHITS && p < KNN_K) {
        float dd = g_dist[(size_t)hit * KNN_K + p];
        wsh[h][p] = expf(-10.0f * dd);
        nsh[h][p] = g_nidx[(size_t)hit * KNN_K + p];
    }
    __syncthreads();
    if (hit >= NHITS) return;

    float acc = 0.0f;
    float mx = -INFINITY;
#pragma unroll 8
    for (int k = 0; k < KNN_K; k++) {
        float f = g_feat[(size_t)nsh[h][k] * PROP + p];
        float v = f * wsh[h][k];
        acc += v;
        mx = fmaxf(mx, v);
    }
    float fs = g_feat[(size_t)hit * PROP + p];
    float* arow = &g_a[(size_t)hit * AIN];
    arow[p]        = acc / (float)KNN_K - fs;
    arow[PROP + p] = mx - fs;
    arow[2 * PROP + p] = x[hit * FIN + p];
}

// ---------------------------------------------------------------------------
// K4: out = tanh(a @ W_out + b_out), [60000,192] x [192,128].
// ---------------------------------------------------------------------------
#define GM 128
#define GK 16

__global__ __launch_bounds__(256)
void k_gemm(const float* __restrict__ W, const float* __restrict__ bias,
            float* __restrict__ out)
{
    __shared__ float As[GK][GM + 4];
    __shared__ float Bs[GK][FOUT];

    int tid = threadIdx.x;
    int tx = tid & 15;
    int ty = tid >> 4;
    int rowBase = blockIdx.x * GM;

    float acc[8][8];
#pragma unroll
    for (int i = 0; i < 8; i++)
#pragma unroll
        for (int j = 0; j < 8; j++) acc[i][j] = 0.0f;

    for (int kt = 0; kt < AIN; kt += GK) {
#pragma unroll
        for (int l = 0; l < 2; l++) {
            int id = tid + l * 256;
            int r = id >> 2;
            int c4 = (id & 3) * 4;
            int grow = rowBase + r;
            float4 v = make_float4(0.f, 0.f, 0.f, 0.f);
            if (grow < NHITS)
                v = *(const float4*)&g_a[(size_t)grow * AIN + kt + c4];
            As[c4 + 0][r] = v.x;
            As[c4 + 1][r] = v.y;
            As[c4 + 2][r] = v.z;
            As[c4 + 3][r] = v.w;
        }
#pragma unroll
        for (int l = 0; l < 2; l++) {
            int id = tid + l * 256;
            int r = id >> 5;
            int c = (id & 31) * 4;
            *(float4*)&Bs[r][c] = *(const float4*)&W[(size_t)(kt + r) * FOUT + c];
        }
        __syncthreads();

#pragma unroll
        for (int k = 0; k < GK; k++) {
            float4 a0 = *(const float4*)&As[k][ty * 8];
            float4 a1 = *(const float4*)&As[k][ty * 8 + 4];
            float4 b0 = *(const float4*)&Bs[k][tx * 8];
            float4 b1 = *(const float4*)&Bs[k][tx * 8 + 4];
            float a[8] = {a0.x, a0.y, a0.z, a0.w, a1.x, a1.y, a1.z, a1.w};
            float b[8] = {b0.x, b0.y, b0.z, b0.w, b1.x, b1.y, b1.z, b1.w};
#pragma unroll
            for (int i = 0; i < 8; i++)
#pragma unroll
                for (int j = 0; j < 8; j++)
                    acc[i][j] += a[i] * b[j];
        }
        __syncthreads();
    }

    float bv[8];
#pragma unroll
    for (int j = 0; j < 8; j++) bv[j] = bias[tx * 8 + j];

#pragma unroll
    for (int i = 0; i < 8; i++) {
        int grow = rowBase + ty * 8 + i;
        if (grow < NHITS) {
#pragma unroll
            for (int j = 0; j < 8; j++)
                out[(size_t)grow * FOUT + tx * 8 + j] = tanhf(acc[i][j] + bv[j]);
        }
    }
}

// ---------------------------------------------------------------------------
// launch
// ---------------------------------------------------------------------------
extern "C" void kernel_launch(void* const* d_in, const int* in_sizes, int n_in,
                              void* d_out, int out_size)
{
    const float* x  = (const float*)d_in[0];
    const float* Wp = (const float*)d_in[2];
    const float* bp = (const float*)d_in[3];
    const float* Ws = (const float*)d_in[4];
    const float* bs = (const float*)d_in[5];
    const float* Wo = (const float*)d_in[6];
    const float* bo = (const float*)d_in[7];

    float* out = (float*)d_out;

    const int full_sz = NHITS * (FOUT + DIM + KNN_K + KNN_K);
    bool full = (out_size == full_sz);
    float* coords_out = full ? out + (size_t)NHITS * FOUT : nullptr;
    float* nidx_out   = full ? coords_out + (size_t)NHITS * DIM : nullptr;
    float* dist_out   = full ? nidx_out + (size_t)NHITS * KNN_K : nullptr;

    k_transform<<<NHITS / 4, 256>>>(x, Wp, bp, Ws, bs, coords_out);
    k_soa<<<(NHITS + 255) / 256, 256>>>();
    k_knn<<<dim3((V_EV + KNN_T - 1) / KNN_T, B_EV), KNN_T>>>(nidx_out, dist_out);
    k_agg<<<NHITS / 4, 256>>>(x);
    k_gemm<<<(NHITS + GM - 1) / GM, 256>>>(Wo, bo, out);
}